// round 16
// baseline (speedup 1.0000x reference)
#include <cuda_runtime.h>
#include <cuda_bf16.h>
#include <math.h>
#include <cstdint>

#define B_ 4
#define S_ 2048
#define D_ 2048
#define NH_ 16
#define NKV_ 4
#define HD_ 128
#define GROUPS_ 4
#define MTOK (B_*S_)      /* 8192 */
#define KVD (NKV_*HD_)    /* 512  */

// bf16 hi/lo split buffers
__device__ __nv_bfloat16 g_xh[(size_t)MTOK * D_];
__device__ __nv_bfloat16 g_xl[(size_t)MTOK * D_];
__device__ __nv_bfloat16 g_wqh[(size_t)D_ * D_];
__device__ __nv_bfloat16 g_wql[(size_t)D_ * D_];
__device__ __nv_bfloat16 g_wkh[(size_t)KVD * D_];
__device__ __nv_bfloat16 g_wkl[(size_t)KVD * D_];
__device__ __nv_bfloat16 g_wvh[(size_t)KVD * D_];
__device__ __nv_bfloat16 g_wvl[(size_t)KVD * D_];
__device__ __nv_bfloat16 g_woh[(size_t)D_ * D_];
__device__ __nv_bfloat16 g_wol[(size_t)D_ * D_];
__device__ __nv_bfloat16 g_ch[(size_t)MTOK * D_];
__device__ __nv_bfloat16 g_cl[(size_t)MTOK * D_];

// bf16 hi/lo attention operands (rope applied in qkv epilogue; q pre-scaled)
__device__ __nv_bfloat16 g_qh[(size_t)MTOK * D_];
__device__ __nv_bfloat16 g_ql[(size_t)MTOK * D_];
__device__ __nv_bfloat16 g_kh[(size_t)MTOK * KVD];
__device__ __nv_bfloat16 g_kl[(size_t)MTOK * KVD];
__device__ __nv_bfloat16 g_vh[(size_t)MTOK * KVD];
__device__ __nv_bfloat16 g_vl[(size_t)MTOK * KVD];

// ============================================================================
// helpers (portable PTX only)
// ============================================================================
__device__ __forceinline__ uint32_t smem_u32(const void* p) {
    uint32_t a;
    asm("{ .reg .u64 t; cvta.to.shared.u64 t, %1; cvt.u32.u64 %0, t; }"
        : "=r"(a) : "l"(p));
    return a;
}
__device__ __forceinline__ uint32_t lds32(uint32_t a) {
    uint32_t v;
    asm volatile("ld.shared.b32 %0, [%1];" : "=r"(v) : "r"(a));
    return v;
}
__device__ __forceinline__ void cp16(uint32_t dst, const void* src) {
    asm volatile("cp.async.cg.shared.global [%0], [%1], 16;"
                 :: "r"(dst), "l"(src) : "memory");
}
__device__ __forceinline__ void mma_bf16(float* c,
    uint32_t a0, uint32_t a1, uint32_t a2, uint32_t a3,
    uint32_t b0, uint32_t b1)
{
    asm volatile(
        "mma.sync.aligned.m16n8k16.row.col.f32.bf16.bf16.f32 "
        "{%0,%1,%2,%3}, {%4,%5,%6,%7}, {%8,%9}, {%0,%1,%2,%3};"
        : "+f"(c[0]), "+f"(c[1]), "+f"(c[2]), "+f"(c[3])
        : "r"(a0), "r"(a1), "r"(a2), "r"(a3), "r"(b0), "r"(b1));
}
__device__ __forceinline__ void ldmx4(uint32_t* d, uint32_t a) {
    asm volatile(
        "ldmatrix.sync.aligned.m8n8.x4.shared.b16 {%0,%1,%2,%3}, [%4];"
        : "=r"(d[0]), "=r"(d[1]), "=r"(d[2]), "=r"(d[3]) : "r"(a));
}
__device__ __forceinline__ void ldmx4t(uint32_t& d0, uint32_t& d1,
                                       uint32_t& d2, uint32_t& d3, uint32_t a)
{
    asm volatile(
        "ldmatrix.sync.aligned.m8n8.x4.trans.shared.b16 {%0,%1,%2,%3}, [%4];"
        : "=r"(d0), "=r"(d1), "=r"(d2), "=r"(d3) : "r"(a));
}

// ============================================================================
// split: fp32 -> hi bf16 + lo bf16
// ============================================================================
__global__ void split_bf16(const float* __restrict__ in,
                           __nv_bfloat16* __restrict__ hi,
                           __nv_bfloat16* __restrict__ lo, int n)
{
    const int i = (blockIdx.x * blockDim.x + threadIdx.x) * 4;
    if (i >= n) return;
    float4 v = *(const float4*)(in + i);
    __nv_bfloat16 h0 = __float2bfloat16(v.x);
    __nv_bfloat16 h1 = __float2bfloat16(v.y);
    __nv_bfloat16 h2 = __float2bfloat16(v.z);
    __nv_bfloat16 h3 = __float2bfloat16(v.w);
    __nv_bfloat16 l0 = __float2bfloat16(v.x - __bfloat162float(h0));
    __nv_bfloat16 l1 = __float2bfloat16(v.y - __bfloat162float(h1));
    __nv_bfloat16 l2 = __float2bfloat16(v.z - __bfloat162float(h2));
    __nv_bfloat16 l3 = __float2bfloat16(v.w - __bfloat162float(h3));
    __nv_bfloat162* H = (__nv_bfloat162*)(hi + i);
    __nv_bfloat162* L = (__nv_bfloat162*)(lo + i);
    H[0] = __halves2bfloat162(h0, h1);
    H[1] = __halves2bfloat162(h2, h3);
    L[0] = __halves2bfloat162(l0, l1);
    L[1] = __halves2bfloat162(l2, l3);
}

// ============================================================================
// GEMM mainloop pieces: CTA 128x128, K-chunk 32, 8 warps, 2 CTA/SM.
// MMA emission is term-major within each mt (same-acc reuse distance 4;
// per-accumulator term order unchanged -> bitwise-identical result).
// ============================================================================
#define RSTR 80
#define MATB (128 * RSTR)
#define STG  (4 * MATB)
#define SMEM_GEMM (2 * STG)
#define EPSTR 132

// ============================================================================
// Fused QKV GEMM + RoPE-in-epilogue
// ============================================================================
__global__ __launch_bounds__(256, 2) void qkv_gemm(
    const __nv_bfloat16* __restrict__ xh, const __nv_bfloat16* __restrict__ xl,
    const __nv_bfloat16* __restrict__ wqh, const __nv_bfloat16* __restrict__ wql,
    const __nv_bfloat16* __restrict__ wkh, const __nv_bfloat16* __restrict__ wkl,
    const __nv_bfloat16* __restrict__ wvh, const __nv_bfloat16* __restrict__ wvl,
    const float* __restrict__ wq_b, const float* __restrict__ wk_b,
    const float* __restrict__ wv_b,
    __nv_bfloat16* __restrict__ outQh, __nv_bfloat16* __restrict__ outQl,
    __nv_bfloat16* __restrict__ outKh, __nv_bfloat16* __restrict__ outKl,
    __nv_bfloat16* __restrict__ outVh, __nv_bfloat16* __restrict__ outVl)
{
    extern __shared__ char smc[];
    const uint32_t sb = smem_u32(smc);
    const int tid = threadIdx.x;
    const int wid = tid >> 5, lane = tid & 31;
    const int wm = wid & 1, wn = wid >> 1;
    const int g = lane >> 2, tg = lane & 3;
    const int lrow = ((lane >> 3) & 1) * 8 + (lane & 7);
    const int lcol = (lane >> 4) * 16;
    const int K = D_;

    const int tile = blockIdx.x;
    int which, bm, bn, N;
    const __nv_bfloat16 *Bh, *Bl;
    const float* bias;
    if (tile < 1024) {
        which = 0; bm = (tile >> 4) * 128; bn = (tile & 15) * 128; N = D_;
        Bh = wqh; Bl = wql; bias = wq_b;
    } else if (tile < 1280) {
        const int t = tile - 1024;
        which = 1; bm = (t >> 2) * 128; bn = (t & 3) * 128; N = KVD;
        Bh = wkh; Bl = wkl; bias = wk_b;
    } else {
        const int t = tile - 1280;
        which = 2; bm = (t >> 2) * 128; bn = (t & 3) * 128; N = KVD;
        Bh = wvh; Bl = wvl; bias = wv_b;
    }

    float acc[4][4][4];
    #pragma unroll
    for (int i = 0; i < 4; i++)
        #pragma unroll
        for (int j = 0; j < 4; j++)
            #pragma unroll
            for (int r = 0; r < 4; r++) acc[i][j][r] = 0.0f;

    const int T = K / 32;

    auto issue = [&](int s, int k0) {
        const uint32_t sbase = sb + s * STG;
        #pragma unroll
        for (int i = 0; i < 2; i++) {
            const int idx = tid + i * 256;
            const int row = idx >> 2, c8 = idx & 3;
            const size_t goA = (size_t)(bm + row) * K + k0 + c8 * 8;
            const size_t goB = (size_t)(bn + row) * K + k0 + c8 * 8;
            const uint32_t so = (uint32_t)(row * RSTR + c8 * 16);
            cp16(sbase + so,            xh + goA);
            cp16(sbase + MATB + so,     xl + goA);
            cp16(sbase + 2 * MATB + so, Bh + goB);
            cp16(sbase + 3 * MATB + so, Bl + goB);
        }
        asm volatile("cp.async.commit_group;" ::: "memory");
    };

    issue(0, 0);

    for (int t = 0; t < T; t++) {
        asm volatile("cp.async.wait_group 0;" ::: "memory");
        __syncthreads();
        if (t + 1 < T) issue((t + 1) & 1, (t + 1) * 32);

        const uint32_t stb = sb + (t & 1) * STG;
        const uint32_t aLdm = stb + (uint32_t)((wm * 64 + lrow) * RSTR + lcol);
        const uint32_t bB = stb + 2 * MATB + (uint32_t)((wn * 32 + g) * RSTR + tg * 4);

        #pragma unroll
        for (int ks = 0; ks < 2; ks++) {
            const uint32_t ko = ks * 32;
            uint32_t bh[4][2], bl[4][2];
            #pragma unroll
            for (int nt = 0; nt < 4; nt++) {
                const uint32_t a = bB + nt * 8 * RSTR + ko;
                bh[nt][0] = lds32(a);
                bh[nt][1] = lds32(a + 16);
                bl[nt][0] = lds32(a + MATB);
                bl[nt][1] = lds32(a + MATB + 16);
            }
            #pragma unroll
            for (int mt = 0; mt < 4; mt++) {
                uint32_t ah[4], al[4];
                ldmx4(ah, aLdm + mt * 16 * RSTR + ko);
                ldmx4(al, aLdm + MATB + mt * 16 * RSTR + ko);
                // term-major: same-acc reuse distance 4; per-acc order
                // (ah*bh, ah*bl, al*bh) preserved -> bitwise identical
                #pragma unroll
                for (int nt = 0; nt < 4; nt++)
                    mma_bf16(acc[mt][nt], ah[0], ah[1], ah[2], ah[3],
                             bh[nt][0], bh[nt][1]);
                #pragma unroll
                for (int nt = 0; nt < 4; nt++)
                    mma_bf16(acc[mt][nt], ah[0], ah[1], ah[2], ah[3],
                             bl[nt][0], bl[nt][1]);
                #pragma unroll
                for (int nt = 0; nt < 4; nt++)
                    mma_bf16(acc[mt][nt], al[0], al[1], al[2], al[3],
                             bh[nt][0], bh[nt][1]);
            }
        }
    }
    __syncthreads();

    if (which == 2) {
        #pragma unroll
        for (int mt = 0; mt < 4; mt++) {
            const int r0 = bm + wm * 64 + mt * 16 + g;
            #pragma unroll
            for (int nt = 0; nt < 4; nt++) {
                const int col = bn + wn * 32 + nt * 8 + tg * 2;
                const float b0 = bias[col], b1 = bias[col + 1];
                const float v00 = acc[mt][nt][0] + b0, v01 = acc[mt][nt][1] + b1;
                const float v10 = acc[mt][nt][2] + b0, v11 = acc[mt][nt][3] + b1;
                __nv_bfloat162 h0 = __floats2bfloat162_rn(v00, v01);
                float2 f0 = __bfloat1622float2(h0);
                __nv_bfloat162 l0 = __floats2bfloat162_rn(v00 - f0.x, v01 - f0.y);
                __nv_bfloat162 h1 = __floats2bfloat162_rn(v10, v11);
                float2 f1 = __bfloat1622float2(h1);
                __nv_bfloat162 l1 = __floats2bfloat162_rn(v10 - f1.x, v11 - f1.y);
                *(__nv_bfloat162*)&outVh[(size_t)r0 * N + col]       = h0;
                *(__nv_bfloat162*)&outVl[(size_t)r0 * N + col]       = l0;
                *(__nv_bfloat162*)&outVh[(size_t)(r0 + 8) * N + col] = h1;
                *(__nv_bfloat162*)&outVl[(size_t)(r0 + 8) * N + col] = l1;
            }
        }
        return;
    }

    float* stg = (float*)smc;
    #pragma unroll
    for (int mt = 0; mt < 4; mt++) {
        const int lr0 = wm * 64 + mt * 16 + g;
        #pragma unroll
        for (int nt = 0; nt < 4; nt++) {
            const int lc = wn * 32 + nt * 8 + tg * 2;
            const float b0 = bias[bn + lc], b1 = bias[bn + lc + 1];
            stg[lr0 * EPSTR + lc]           = acc[mt][nt][0] + b0;
            stg[lr0 * EPSTR + lc + 1]       = acc[mt][nt][1] + b1;
            stg[(lr0 + 8) * EPSTR + lc]     = acc[mt][nt][2] + b0;
            stg[(lr0 + 8) * EPSTR + lc + 1] = acc[mt][nt][3] + b1;
        }
    }
    __syncthreads();

    const float scale = (which == 0) ? 0.08838834764831845f : 1.0f;
    __nv_bfloat16* oh = (which == 0) ? outQh : outKh;
    __nv_bfloat16* ol = (which == 0) ? outQl : outKl;

    #pragma unroll 4
    for (int i = 0; i < 32; i++) {
        const int idx = tid + i * 256;
        const int row = idx >> 6;
        const int c = idx & 63;
        const int tok = bm + row;
        const int s = tok & (S_ - 1);

        const float expo = (float)(2 * c) / 128.0f;
        const float inv = 1.0f / powf(1.0e6f, expo);
        float sn, cs;
        sincosf((float)s * inv, &sn, &cs);

        const float x1 = stg[row * EPSTR + c];
        const float x2 = stg[row * EPSTR + c + 64];
        const float y1 = (x1 * cs - x2 * sn) * scale;
        const float y2 = (x2 * cs + x1 * sn) * scale;

        const __nv_bfloat16 h1 = __float2bfloat16(y1);
        const __nv_bfloat16 l1 = __float2bfloat16(y1 - __bfloat162float(h1));
        const __nv_bfloat16 h2 = __float2bfloat16(y2);
        const __nv_bfloat16 l2 = __float2bfloat16(y2 - __bfloat162float(h2));

        const size_t o1 = (size_t)tok * N + bn + c;
        oh[o1] = h1;  ol[o1] = l1;
        oh[o1 + 64] = h2;  ol[o1 + 64] = l2;
    }
}

// ============================================================================
// Out-projection GEMM (term-major MMA emission, same transformation)
// ============================================================================
__global__ __launch_bounds__(256, 2) void gemm_bf16x3(
    const __nv_bfloat16* __restrict__ Ah, const __nv_bfloat16* __restrict__ Al,
    const __nv_bfloat16* __restrict__ Bh, const __nv_bfloat16* __restrict__ Bl,
    float* __restrict__ C, int M, int N, int K)
{
    extern __shared__ char smc[];
    const uint32_t sb = smem_u32(smc);
    const int tid = threadIdx.x;
    const int wid = tid >> 5, lane = tid & 31;
    const int bm = blockIdx.y * 128, bn = blockIdx.x * 128;
    const int wm = wid & 1, wn = wid >> 1;
    const int g = lane >> 2, tg = lane & 3;
    const int lrow = ((lane >> 3) & 1) * 8 + (lane & 7);
    const int lcol = (lane >> 4) * 16;

    float acc[4][4][4];
    #pragma unroll
    for (int i = 0; i < 4; i++)
        #pragma unroll
        for (int j = 0; j < 4; j++)
            #pragma unroll
            for (int r = 0; r < 4; r++) acc[i][j][r] = 0.0f;

    const int T = K / 32;

    auto issue = [&](int s, int k0) {
        const uint32_t sbase = sb + s * STG;
        #pragma unroll
        for (int i = 0; i < 2; i++) {
            const int idx = tid + i * 256;
            const int row = idx >> 2, c8 = idx & 3;
            const size_t goA = (size_t)(bm + row) * K + k0 + c8 * 8;
            const size_t goB = (size_t)(bn + row) * K + k0 + c8 * 8;
            const uint32_t so = (uint32_t)(row * RSTR + c8 * 16);
            cp16(sbase + so,            Ah + goA);
            cp16(sbase + MATB + so,     Al + goA);
            cp16(sbase + 2 * MATB + so, Bh + goB);
            cp16(sbase + 3 * MATB + so, Bl + goB);
        }
        asm volatile("cp.async.commit_group;" ::: "memory");
    };

    issue(0, 0);

    for (int t = 0; t < T; t++) {
        asm volatile("cp.async.wait_group 0;" ::: "memory");
        __syncthreads();
        if (t + 1 < T) issue((t + 1) & 1, (t + 1) * 32);

        const uint32_t stb = sb + (t & 1) * STG;
        const uint32_t aLdm = stb + (uint32_t)((wm * 64 + lrow) * RSTR + lcol);
        const uint32_t bB = stb + 2 * MATB + (uint32_t)((wn * 32 + g) * RSTR + tg * 4);

        #pragma unroll
        for (int ks = 0; ks < 2; ks++) {
            const uint32_t ko = ks * 32;
            uint32_t bh[4][2], bl[4][2];
            #pragma unroll
            for (int nt = 0; nt < 4; nt++) {
                const uint32_t a = bB + nt * 8 * RSTR + ko;
                bh[nt][0] = lds32(a);
                bh[nt][1] = lds32(a + 16);
                bl[nt][0] = lds32(a + MATB);
                bl[nt][1] = lds32(a + MATB + 16);
            }
            #pragma unroll
            for (int mt = 0; mt < 4; mt++) {
                uint32_t ah[4], al[4];
                ldmx4(ah, aLdm + mt * 16 * RSTR + ko);
                ldmx4(al, aLdm + MATB + mt * 16 * RSTR + ko);
                #pragma unroll
                for (int nt = 0; nt < 4; nt++)
                    mma_bf16(acc[mt][nt], ah[0], ah[1], ah[2], ah[3],
                             bh[nt][0], bh[nt][1]);
                #pragma unroll
                for (int nt = 0; nt < 4; nt++)
                    mma_bf16(acc[mt][nt], ah[0], ah[1], ah[2], ah[3],
                             bl[nt][0], bl[nt][1]);
                #pragma unroll
                for (int nt = 0; nt < 4; nt++)
                    mma_bf16(acc[mt][nt], al[0], al[1], al[2], al[3],
                             bh[nt][0], bh[nt][1]);
            }
        }
    }

    #pragma unroll
    for (int mt = 0; mt < 4; mt++) {
        const int r0 = bm + wm * 64 + mt * 16 + g;
        #pragma unroll
        for (int nt = 0; nt < 4; nt++) {
            const int col = bn + wn * 32 + nt * 8 + tg * 2;
            *(float2*)&C[(size_t)r0 * N + col] =
                make_float2(acc[mt][nt][0], acc[mt][nt][1]);
            *(float2*)&C[(size_t)(r0 + 8) * N + col] =
                make_float2(acc[mt][nt][2], acc[mt][nt][3]);
        }
    }
}

// ============================================================================
// Tensor-core flash attention v3 (R15, unchanged): 128 q-rows, 8 warps,
// KV double-buffered single-sync.
// ============================================================================
#define FSTRB 272
#define FQTILE (128 * FSTRB)
#define FKTILE (64 * FSTRB)
#define FKSTG  (4 * FKTILE)
#define FSMEM (2 * FQTILE + 2 * FKSTG)

__global__ __launch_bounds__(256, 1) void flash_mma()
{
    extern __shared__ char smf[];
    const uint32_t sb = smem_u32(smf);
    const uint32_t QH = 0, QL = FQTILE;
    const uint32_t KV0 = 2 * FQTILE;

    const int qt = blockIdx.x, h = blockIdx.y, b = blockIdx.z;
    const int kvh = h >> 2;
    const int tid = threadIdx.x;
    const int w = tid >> 5, lane = tid & 31;
    const int g = lane >> 2, tg = lane & 3;

    const size_t kvoff = ((size_t)b * S_ * NKV_ + kvh) * HD_;
    const __nv_bfloat16* khp = g_kh + kvoff;
    const __nv_bfloat16* klp = g_kl + kvoff;
    const __nv_bfloat16* vhp = g_vh + kvoff;
    const __nv_bfloat16* vlp = g_vl + kvoff;

    auto issue_kv = [&](int jt) {
        const uint32_t kb = KV0 + (jt & 1) * FKSTG;
        const size_t tb = (size_t)(jt * 64) * KVD;
        #pragma unroll
        for (int i = 0; i < 4; i++) {
            const int c = tid + i * 256;
            const int row = c >> 4, o16 = c & 15;
            const uint32_t so = (uint32_t)(row * FSTRB + o16 * 16);
            const size_t go = tb + (size_t)row * KVD + o16 * 8;
            cp16(sb + kb + so,              khp + go);
            cp16(sb + kb + FKTILE + so,     klp + go);
            cp16(sb + kb + 2 * FKTILE + so, vhp + go);
            cp16(sb + kb + 3 * FKTILE + so, vlp + go);
        }
        asm volatile("cp.async.commit_group;" ::: "memory");
    };

    {
        const size_t qoff = (((size_t)(b * S_ + qt * 128)) * NH_ + h) * HD_;
        const __nv_bfloat16* qhp = g_qh + qoff;
        const __nv_bfloat16* qlp = g_ql + qoff;
        #pragma unroll
        for (int i = 0; i < 8; i++) {
            const int c = tid + i * 256;
            const int row = c >> 4, o16 = c & 15;
            const uint32_t so = (uint32_t)(row * FSTRB + o16 * 16);
            const size_t go = (size_t)row * (NH_ * HD_) + o16 * 8;
            cp16(sb + QH + so, qhp + go);
            cp16(sb + QL + so, qlp + go);
        }
        asm volatile("cp.async.commit_group;" ::: "memory");
    }
    issue_kv(0);

    float o[16][4];
    #pragma unroll
    for (int n = 0; n < 16; n++)
        #pragma unroll
        for (int c = 0; c < 4; c++) o[n][c] = 0.0f;
    float m0 = -1e30f, m1 = -1e30f, l0 = 0.0f, l1 = 0.0f;

    const int r0l = 16 * w + g;
    const int row_g0 = qt * 128 + r0l;
    const int jtmax = 2 * qt + 1;

    for (int jt = 0; jt <= jtmax; jt++) {
        asm volatile("cp.async.wait_group 0;" ::: "memory");
        __syncthreads();
        if (jt + 1 <= jtmax) issue_kv(jt + 1);

        const uint32_t KH = KV0 + (jt & 1) * FKSTG;
        const uint32_t VH = KH + 2 * FKTILE;

        float sacc[8][4];
        #pragma unroll
        for (int n = 0; n < 8; n++)
            #pragma unroll
            for (int c = 0; c < 4; c++) sacc[n][c] = 0.0f;

        const uint32_t qrow = sb + QH + (uint32_t)((16 * w + g) * FSTRB + tg * 4);
        #pragma unroll
        for (int k0 = 0; k0 < 8; k0++) {
            const uint32_t qa = qrow + k0 * 32;
            const uint32_t ah0 = lds32(qa);
            const uint32_t ah1 = lds32(qa + 8 * FSTRB);
            const uint32_t ah2 = lds32(qa + 16);
            const uint32_t ah3 = lds32(qa + 8 * FSTRB + 16);
            const uint32_t al0 = lds32(qa + FQTILE);
            const uint32_t al1 = lds32(qa + FQTILE + 8 * FSTRB);
            const uint32_t al2 = lds32(qa + FQTILE + 16);
            const uint32_t al3 = lds32(qa + FQTILE + 8 * FSTRB + 16);
            #pragma unroll
            for (int n = 0; n < 8; n++) {
                const uint32_t kb = sb + KH +
                    (uint32_t)((n * 8 + g) * FSTRB + k0 * 32 + tg * 4);
                const uint32_t bh0 = lds32(kb);
                const uint32_t bh1 = lds32(kb + 16);
                const uint32_t bl0 = lds32(kb + FKTILE);
                const uint32_t bl1 = lds32(kb + FKTILE + 16);
                mma_bf16(sacc[n], ah0, ah1, ah2, ah3, bh0, bh1);
                mma_bf16(sacc[n], ah0, ah1, ah2, ah3, bl0, bl1);
                mma_bf16(sacc[n], al0, al1, al2, al3, bh0, bh1);
            }
        }

        if (jt >= 2 * qt) {
            #pragma unroll
            for (int n = 0; n < 8; n++) {
                const int col_g = jt * 64 + n * 8 + 2 * tg;
                if (col_g     > row_g0)     sacc[n][0] = -1e30f;
                if (col_g + 1 > row_g0)     sacc[n][1] = -1e30f;
                if (col_g     > row_g0 + 8) sacc[n][2] = -1e30f;
                if (col_g + 1 > row_g0 + 8) sacc[n][3] = -1e30f;
            }
        }

        float mx0 = -1e30f, mx1 = -1e30f;
        #pragma unroll
        for (int n = 0; n < 8; n++) {
            mx0 = fmaxf(mx0, fmaxf(sacc[n][0], sacc[n][1]));
            mx1 = fmaxf(mx1, fmaxf(sacc[n][2], sacc[n][3]));
        }
        mx0 = fmaxf(mx0, __shfl_xor_sync(0xffffffffu, mx0, 1));
        mx0 = fmaxf(mx0, __shfl_xor_sync(0xffffffffu, mx0, 2));
        mx1 = fmaxf(mx1, __shfl_xor_sync(0xffffffffu, mx1, 1));
        mx1 = fmaxf(mx1, __shfl_xor_sync(0xffffffffu, mx1, 2));
        const float nm0 = fmaxf(m0, mx0), nm1 = fmaxf(m1, mx1);
        const float a0 = __expf(m0 - nm0), a1 = __expf(m1 - nm1);
        m0 = nm0; m1 = nm1;

        float s0 = 0.0f, s1 = 0.0f;
        #pragma unroll
        for (int n = 0; n < 8; n++) {
            sacc[n][0] = __expf(sacc[n][0] - nm0);
            sacc[n][1] = __expf(sacc[n][1] - nm0);
            sacc[n][2] = __expf(sacc[n][2] - nm1);
            sacc[n][3] = __expf(sacc[n][3] - nm1);
            s0 += sacc[n][0] + sacc[n][1];
            s1 += sacc[n][2] + sacc[n][3];
        }
        s0 += __shfl_xor_sync(0xffffffffu, s0, 1);
        s0 += __shfl_xor_sync(0xffffffffu, s0, 2);
        s1 += __shfl_xor_sync(0xffffffffu, s1, 1);
        s1 += __shfl_xor_sync(0xffffffffu, s1, 2);
        l0 = l0 * a0 + s0;
        l1 = l1 * a1 + s1;

        #pragma unroll
        for (int n = 0; n < 16; n++) {
            o[n][0] *= a0; o[n][1] *= a0;
            o[n][2] *= a1; o[n][3] *= a1;
        }

        const int mset = lane >> 3, r = lane & 7;
        #pragma unroll
        for (int kt = 0; kt < 4; kt++) {
            __nv_bfloat162 t0 = __floats2bfloat162_rn(sacc[2*kt][0],   sacc[2*kt][1]);
            __nv_bfloat162 t1 = __floats2bfloat162_rn(sacc[2*kt][2],   sacc[2*kt][3]);
            __nv_bfloat162 t2 = __floats2bfloat162_rn(sacc[2*kt+1][0], sacc[2*kt+1][1]);
            __nv_bfloat162 t3 = __floats2bfloat162_rn(sacc[2*kt+1][2], sacc[2*kt+1][3]);
            float2 f0 = __bfloat1622float2(t0), f1 = __bfloat1622float2(t1);
            float2 f2 = __bfloat1622float2(t2), f3 = __bfloat1622float2(t3);
            __nv_bfloat162 u0 = __floats2bfloat162_rn(sacc[2*kt][0]-f0.x,   sacc[2*kt][1]-f0.y);
            __nv_bfloat162 u1 = __floats2bfloat162_rn(sacc[2*kt][2]-f1.x,   sacc[2*kt][3]-f1.y);
            __nv_bfloat162 u2 = __floats2bfloat162_rn(sacc[2*kt+1][0]-f2.x, sacc[2*kt+1][1]-f2.y);
            __nv_bfloat162 u3 = __floats2bfloat162_rn(sacc[2*kt+1][2]-f3.x, sacc[2*kt+1][3]-f3.y);
            const uint32_t ph0 = *(uint32_t*)&t0, ph1 = *(uint32_t*)&t1;
            const uint32_t ph2 = *(uint32_t*)&t2, ph3 = *(uint32_t*)&t3;
            const uint32_t pl0 = *(uint32_t*)&u0, pl1 = *(uint32_t*)&u1;
            const uint32_t pl2 = *(uint32_t*)&u2, pl3 = *(uint32_t*)&u3;

            const int kk = kt * 16 + (mset & 1) * 8 + r;
            #pragma unroll
            for (int np = 0; np < 8; np++) {
                const int nn = np * 16 + (mset >> 1) * 8;
                const uint32_t va = sb + VH + (uint32_t)(kk * FSTRB + nn * 2);
                uint32_t v0, v1, v2, v3, w0, w1, w2, w3;
                ldmx4t(v0, v1, v2, v3, va);
                ldmx4t(w0, w1, w2, w3, va + FKTILE);
                mma_bf16(o[2*np],   ph0, ph1, ph2, ph3, v0, v1);
                mma_bf16(o[2*np],   ph0, ph1, ph2, ph3, w0, w1);
                mma_bf16(o[2*np],   pl0, pl1, pl2, pl3, v0, v1);
                mma_bf16(o[2*np+1], ph0, ph1, ph2, ph3, v2, v3);
                mma_bf16(o[2*np+1], ph0, ph1, ph2, ph3, w2, w3);
                mma_bf16(o[2*np+1], pl0, pl1, pl2, pl3, v2, v3);
            }
        }
    }

    const float il0 = 1.0f / l0, il1 = 1.0f / l1;
    const size_t base0 = (((size_t)(b * S_ + qt * 128 + 16 * w + g)) * NH_ + h) * HD_;
    const size_t base1 = base0 + (size_t)8 * NH_ * HD_;
    #pragma unroll
    for (int n = 0; n < 16; n++) {
        const int cc = n * 8 + tg * 2;
        const float a0 = o[n][0] * il0, a1 = o[n][1] * il0;
        const float b0v = o[n][2] * il1, b1v = o[n][3] * il1;
        __nv_bfloat162 h0 = __floats2bfloat162_rn(a0, a1);
        float2 f0 = __bfloat1622float2(h0);
        __nv_bfloat162 lo0 = __floats2bfloat162_rn(a0 - f0.x, a1 - f0.y);
        __nv_bfloat162 h1 = __floats2bfloat162_rn(b0v, b1v);
        float2 f1 = __bfloat1622float2(h1);
        __nv_bfloat162 lo1 = __floats2bfloat162_rn(b0v - f1.x, b1v - f1.y);
        *(__nv_bfloat162*)&g_ch[base0 + cc] = h0;
        *(__nv_bfloat162*)&g_cl[base0 + cc] = lo0;
        *(__nv_bfloat162*)&g_ch[base1 + cc] = h1;
        *(__nv_bfloat162*)&g_cl[base1 + cc] = lo1;
    }
}

// ---------------------------------------------------------------------------
extern "C" void kernel_launch(void* const* d_in, const int* in_sizes, int n_in,
                              void* d_out, int out_size)
{
    (void)in_sizes; (void)n_in; (void)out_size;
    const float* x    = (const float*)d_in[0];
    const float* wq_w = (const float*)d_in[1];
    const float* wq_b = (const float*)d_in[2];
    const float* wk_w = (const float*)d_in[3];
    const float* wk_b = (const float*)d_in[4];
    const float* wv_w = (const float*)d_in[5];
    const float* wv_b = (const float*)d_in[6];
    const float* wo_w = (const float*)d_in[7];
    float* out = (float*)d_out;

    __nv_bfloat16 *xh, *xl, *wqh, *wql, *wkh, *wkl, *wvh, *wvl, *woh, *wol, *ch, *cl;
    __nv_bfloat16 *qh, *ql, *kh, *kl, *vh, *vl;
    cudaGetSymbolAddress((void**)&xh,  g_xh);  cudaGetSymbolAddress((void**)&xl,  g_xl);
    cudaGetSymbolAddress((void**)&wqh, g_wqh); cudaGetSymbolAddress((void**)&wql, g_wql);
    cudaGetSymbolAddress((void**)&wkh, g_wkh); cudaGetSymbolAddress((void**)&wkl, g_wkl);
    cudaGetSymbolAddress((void**)&wvh, g_wvh); cudaGetSymbolAddress((void**)&wvl, g_wvl);
    cudaGetSymbolAddress((void**)&woh, g_woh); cudaGetSymbolAddress((void**)&wol, g_wol);
    cudaGetSymbolAddress((void**)&ch,  g_ch);  cudaGetSymbolAddress((void**)&cl,  g_cl);
    cudaGetSymbolAddress((void**)&qh,  g_qh);  cudaGetSymbolAddress((void**)&ql,  g_ql);
    cudaGetSymbolAddress((void**)&kh,  g_kh);  cudaGetSymbolAddress((void**)&kl,  g_kl);
    cudaGetSymbolAddress((void**)&vh,  g_vh);  cudaGetSymbolAddress((void**)&vl,  g_vl);

    cudaFuncSetAttribute(qkv_gemm, cudaFuncAttributeMaxDynamicSharedMemorySize,
                         SMEM_GEMM);
    cudaFuncSetAttribute(gemm_bf16x3, cudaFuncAttributeMaxDynamicSharedMemorySize,
                         SMEM_GEMM);
    cudaFuncSetAttribute(flash_mma, cudaFuncAttributeMaxDynamicSharedMemorySize,
                         FSMEM);

    // hi/lo splits of activations and weights
    split_bf16<<<(MTOK * D_ / 4) / 256, 256>>>(x,    xh,  xl,  MTOK * D_);
    split_bf16<<<(D_ * D_ / 4)   / 256, 256>>>(wq_w, wqh, wql, D_ * D_);
    split_bf16<<<(KVD * D_ / 4)  / 256, 256>>>(wk_w, wkh, wkl, KVD * D_);
    split_bf16<<<(KVD * D_ / 4)  / 256, 256>>>(wv_w, wvh, wvl, KVD * D_);
    split_bf16<<<(D_ * D_ / 4)   / 256, 256>>>(wo_w, woh, wol, D_ * D_);

    // fused QKV projections + RoPE + bf16 split (Q scaled by 1/sqrt(HD))
    qkv_gemm<<<1536, 256, SMEM_GEMM>>>(
        xh, xl, wqh, wql, wkh, wkl, wvh, wvl,
        wq_b, wk_b, wv_b, qh, ql, kh, kl, vh, vl);

    // tensor-core causal GQA flash attention (128 q-rows, KV double-buffered)
    flash_mma<<<dim3(S_ / 128, NH_, B_), 256, FSMEM>>>();

    // output projection (no bias)
    gemm_bf16x3<<<dim3(D_ / 128, MTOK / 128), 256, SMEM_GEMM>>>(
        ch, cl, woh, wol, out, MTOK, D_, D_);
}

// round 17
// speedup vs baseline: 1.0058x; 1.0058x over previous
#include <cuda_runtime.h>
#include <cuda_bf16.h>
#include <math.h>
#include <cstdint>

#define B_ 4
#define S_ 2048
#define D_ 2048
#define NH_ 16
#define NKV_ 4
#define HD_ 128
#define GROUPS_ 4
#define MTOK (B_*S_)      /* 8192 */
#define KVD (NKV_*HD_)    /* 512  */

// bf16 hi/lo split buffers
__device__ __nv_bfloat16 g_xh[(size_t)MTOK * D_];
__device__ __nv_bfloat16 g_xl[(size_t)MTOK * D_];
__device__ __nv_bfloat16 g_wqh[(size_t)D_ * D_];
__device__ __nv_bfloat16 g_wql[(size_t)D_ * D_];
__device__ __nv_bfloat16 g_wkh[(size_t)KVD * D_];
__device__ __nv_bfloat16 g_wkl[(size_t)KVD * D_];
__device__ __nv_bfloat16 g_wvh[(size_t)KVD * D_];
__device__ __nv_bfloat16 g_wvl[(size_t)KVD * D_];
__device__ __nv_bfloat16 g_woh[(size_t)D_ * D_];
__device__ __nv_bfloat16 g_wol[(size_t)D_ * D_];
__device__ __nv_bfloat16 g_ch[(size_t)MTOK * D_];
__device__ __nv_bfloat16 g_cl[(size_t)MTOK * D_];

// bf16 hi/lo attention operands (rope applied in qkv epilogue; q pre-scaled)
__device__ __nv_bfloat16 g_qh[(size_t)MTOK * D_];
__device__ __nv_bfloat16 g_ql[(size_t)MTOK * D_];
__device__ __nv_bfloat16 g_kh[(size_t)MTOK * KVD];
__device__ __nv_bfloat16 g_kl[(size_t)MTOK * KVD];
__device__ __nv_bfloat16 g_vh[(size_t)MTOK * KVD];
__device__ __nv_bfloat16 g_vl[(size_t)MTOK * KVD];

// ============================================================================
// helpers (portable PTX only)
// ============================================================================
__device__ __forceinline__ uint32_t smem_u32(const void* p) {
    uint32_t a;
    asm("{ .reg .u64 t; cvta.to.shared.u64 t, %1; cvt.u32.u64 %0, t; }"
        : "=r"(a) : "l"(p));
    return a;
}
__device__ __forceinline__ uint32_t lds32(uint32_t a) {
    uint32_t v;
    asm volatile("ld.shared.b32 %0, [%1];" : "=r"(v) : "r"(a));
    return v;
}
__device__ __forceinline__ void cp16(uint32_t dst, const void* src) {
    asm volatile("cp.async.cg.shared.global [%0], [%1], 16;"
                 :: "r"(dst), "l"(src) : "memory");
}
__device__ __forceinline__ void mma_bf16(float* c,
    uint32_t a0, uint32_t a1, uint32_t a2, uint32_t a3,
    uint32_t b0, uint32_t b1)
{
    asm volatile(
        "mma.sync.aligned.m16n8k16.row.col.f32.bf16.bf16.f32 "
        "{%0,%1,%2,%3}, {%4,%5,%6,%7}, {%8,%9}, {%0,%1,%2,%3};"
        : "+f"(c[0]), "+f"(c[1]), "+f"(c[2]), "+f"(c[3])
        : "r"(a0), "r"(a1), "r"(a2), "r"(a3), "r"(b0), "r"(b1));
}
__device__ __forceinline__ void ldmx4(uint32_t* d, uint32_t a) {
    asm volatile(
        "ldmatrix.sync.aligned.m8n8.x4.shared.b16 {%0,%1,%2,%3}, [%4];"
        : "=r"(d[0]), "=r"(d[1]), "=r"(d[2]), "=r"(d[3]) : "r"(a));
}
__device__ __forceinline__ void ldmx4t(uint32_t& d0, uint32_t& d1,
                                       uint32_t& d2, uint32_t& d3, uint32_t a)
{
    asm volatile(
        "ldmatrix.sync.aligned.m8n8.x4.trans.shared.b16 {%0,%1,%2,%3}, [%4];"
        : "=r"(d0), "=r"(d1), "=r"(d2), "=r"(d3) : "r"(a));
}

// ============================================================================
// fused split: fp32 -> hi bf16 + lo bf16, all 5 tensors in one launch.
// segment boundaries in float4 blocks of 256 threads:
//  x  : [0, 16384)       (16M elems)
//  wq : [16384, 20480)   (4M)
//  wk : [20480, 21504)   (1M)
//  wv : [21504, 22528)   (1M)
//  wo : [22528, 26624)   (4M)
// ============================================================================
#define SPLIT_GRID 26624

__global__ void split_all(const float* __restrict__ x,
                          const float* __restrict__ wq,
                          const float* __restrict__ wk,
                          const float* __restrict__ wv,
                          const float* __restrict__ wo,
                          __nv_bfloat16* __restrict__ xh, __nv_bfloat16* __restrict__ xl,
                          __nv_bfloat16* __restrict__ wqh, __nv_bfloat16* __restrict__ wql,
                          __nv_bfloat16* __restrict__ wkh, __nv_bfloat16* __restrict__ wkl,
                          __nv_bfloat16* __restrict__ wvh, __nv_bfloat16* __restrict__ wvl,
                          __nv_bfloat16* __restrict__ woh, __nv_bfloat16* __restrict__ wol)
{
    const int blk = blockIdx.x;
    const float* in;
    __nv_bfloat16 *hi, *lo;
    int base;
    if (blk < 16384)      { in = x;  hi = xh;  lo = xl;  base = 0; }
    else if (blk < 20480) { in = wq; hi = wqh; lo = wql; base = 16384; }
    else if (blk < 21504) { in = wk; hi = wkh; lo = wkl; base = 20480; }
    else if (blk < 22528) { in = wv; hi = wvh; lo = wvl; base = 21504; }
    else                  { in = wo; hi = woh; lo = wol; base = 22528; }

    const size_t i = ((size_t)(blk - base) * 256 + threadIdx.x) * 4;
    float4 v = *(const float4*)(in + i);
    __nv_bfloat16 h0 = __float2bfloat16(v.x);
    __nv_bfloat16 h1 = __float2bfloat16(v.y);
    __nv_bfloat16 h2 = __float2bfloat16(v.z);
    __nv_bfloat16 h3 = __float2bfloat16(v.w);
    __nv_bfloat16 l0 = __float2bfloat16(v.x - __bfloat162float(h0));
    __nv_bfloat16 l1 = __float2bfloat16(v.y - __bfloat162float(h1));
    __nv_bfloat16 l2 = __float2bfloat16(v.z - __bfloat162float(h2));
    __nv_bfloat16 l3 = __float2bfloat16(v.w - __bfloat162float(h3));
    __nv_bfloat162* H = (__nv_bfloat162*)(hi + i);
    __nv_bfloat162* L = (__nv_bfloat162*)(lo + i);
    H[0] = __halves2bfloat162(h0, h1);
    H[1] = __halves2bfloat162(h2, h3);
    L[0] = __halves2bfloat162(l0, l1);
    L[1] = __halves2bfloat162(l2, l3);
}

// ============================================================================
// GEMM mainloop pieces (R16): CTA 128x128, K-chunk 32, 8 warps, 2 CTA/SM.
// ============================================================================
#define RSTR 80
#define MATB (128 * RSTR)
#define STG  (4 * MATB)
#define SMEM_GEMM (2 * STG)
#define EPSTR 132

// ============================================================================
// Fused QKV GEMM + RoPE-in-epilogue (R16, unchanged)
// ============================================================================
__global__ __launch_bounds__(256, 2) void qkv_gemm(
    const __nv_bfloat16* __restrict__ xh, const __nv_bfloat16* __restrict__ xl,
    const __nv_bfloat16* __restrict__ wqh, const __nv_bfloat16* __restrict__ wql,
    const __nv_bfloat16* __restrict__ wkh, const __nv_bfloat16* __restrict__ wkl,
    const __nv_bfloat16* __restrict__ wvh, const __nv_bfloat16* __restrict__ wvl,
    const float* __restrict__ wq_b, const float* __restrict__ wk_b,
    const float* __restrict__ wv_b,
    __nv_bfloat16* __restrict__ outQh, __nv_bfloat16* __restrict__ outQl,
    __nv_bfloat16* __restrict__ outKh, __nv_bfloat16* __restrict__ outKl,
    __nv_bfloat16* __restrict__ outVh, __nv_bfloat16* __restrict__ outVl)
{
    extern __shared__ char smc[];
    const uint32_t sb = smem_u32(smc);
    const int tid = threadIdx.x;
    const int wid = tid >> 5, lane = tid & 31;
    const int wm = wid & 1, wn = wid >> 1;
    const int g = lane >> 2, tg = lane & 3;
    const int lrow = ((lane >> 3) & 1) * 8 + (lane & 7);
    const int lcol = (lane >> 4) * 16;
    const int K = D_;

    const int tile = blockIdx.x;
    int which, bm, bn, N;
    const __nv_bfloat16 *Bh, *Bl;
    const float* bias;
    if (tile < 1024) {
        which = 0; bm = (tile >> 4) * 128; bn = (tile & 15) * 128; N = D_;
        Bh = wqh; Bl = wql; bias = wq_b;
    } else if (tile < 1280) {
        const int t = tile - 1024;
        which = 1; bm = (t >> 2) * 128; bn = (t & 3) * 128; N = KVD;
        Bh = wkh; Bl = wkl; bias = wk_b;
    } else {
        const int t = tile - 1280;
        which = 2; bm = (t >> 2) * 128; bn = (t & 3) * 128; N = KVD;
        Bh = wvh; Bl = wvl; bias = wv_b;
    }

    float acc[4][4][4];
    #pragma unroll
    for (int i = 0; i < 4; i++)
        #pragma unroll
        for (int j = 0; j < 4; j++)
            #pragma unroll
            for (int r = 0; r < 4; r++) acc[i][j][r] = 0.0f;

    const int T = K / 32;

    auto issue = [&](int s, int k0) {
        const uint32_t sbase = sb + s * STG;
        #pragma unroll
        for (int i = 0; i < 2; i++) {
            const int idx = tid + i * 256;
            const int row = idx >> 2, c8 = idx & 3;
            const size_t goA = (size_t)(bm + row) * K + k0 + c8 * 8;
            const size_t goB = (size_t)(bn + row) * K + k0 + c8 * 8;
            const uint32_t so = (uint32_t)(row * RSTR + c8 * 16);
            cp16(sbase + so,            xh + goA);
            cp16(sbase + MATB + so,     xl + goA);
            cp16(sbase + 2 * MATB + so, Bh + goB);
            cp16(sbase + 3 * MATB + so, Bl + goB);
        }
        asm volatile("cp.async.commit_group;" ::: "memory");
    };

    issue(0, 0);

    for (int t = 0; t < T; t++) {
        asm volatile("cp.async.wait_group 0;" ::: "memory");
        __syncthreads();
        if (t + 1 < T) issue((t + 1) & 1, (t + 1) * 32);

        const uint32_t stb = sb + (t & 1) * STG;
        const uint32_t aLdm = stb + (uint32_t)((wm * 64 + lrow) * RSTR + lcol);
        const uint32_t bB = stb + 2 * MATB + (uint32_t)((wn * 32 + g) * RSTR + tg * 4);

        #pragma unroll
        for (int ks = 0; ks < 2; ks++) {
            const uint32_t ko = ks * 32;
            uint32_t bh[4][2], bl[4][2];
            #pragma unroll
            for (int nt = 0; nt < 4; nt++) {
                const uint32_t a = bB + nt * 8 * RSTR + ko;
                bh[nt][0] = lds32(a);
                bh[nt][1] = lds32(a + 16);
                bl[nt][0] = lds32(a + MATB);
                bl[nt][1] = lds32(a + MATB + 16);
            }
            #pragma unroll
            for (int mt = 0; mt < 4; mt++) {
                uint32_t ah[4], al[4];
                ldmx4(ah, aLdm + mt * 16 * RSTR + ko);
                ldmx4(al, aLdm + MATB + mt * 16 * RSTR + ko);
                #pragma unroll
                for (int nt = 0; nt < 4; nt++)
                    mma_bf16(acc[mt][nt], ah[0], ah[1], ah[2], ah[3],
                             bh[nt][0], bh[nt][1]);
                #pragma unroll
                for (int nt = 0; nt < 4; nt++)
                    mma_bf16(acc[mt][nt], ah[0], ah[1], ah[2], ah[3],
                             bl[nt][0], bl[nt][1]);
                #pragma unroll
                for (int nt = 0; nt < 4; nt++)
                    mma_bf16(acc[mt][nt], al[0], al[1], al[2], al[3],
                             bh[nt][0], bh[nt][1]);
            }
        }
    }
    __syncthreads();

    if (which == 2) {
        #pragma unroll
        for (int mt = 0; mt < 4; mt++) {
            const int r0 = bm + wm * 64 + mt * 16 + g;
            #pragma unroll
            for (int nt = 0; nt < 4; nt++) {
                const int col = bn + wn * 32 + nt * 8 + tg * 2;
                const float b0 = bias[col], b1 = bias[col + 1];
                const float v00 = acc[mt][nt][0] + b0, v01 = acc[mt][nt][1] + b1;
                const float v10 = acc[mt][nt][2] + b0, v11 = acc[mt][nt][3] + b1;
                __nv_bfloat162 h0 = __floats2bfloat162_rn(v00, v01);
                float2 f0 = __bfloat1622float2(h0);
                __nv_bfloat162 l0 = __floats2bfloat162_rn(v00 - f0.x, v01 - f0.y);
                __nv_bfloat162 h1 = __floats2bfloat162_rn(v10, v11);
                float2 f1 = __bfloat1622float2(h1);
                __nv_bfloat162 l1 = __floats2bfloat162_rn(v10 - f1.x, v11 - f1.y);
                *(__nv_bfloat162*)&outVh[(size_t)r0 * N + col]       = h0;
                *(__nv_bfloat162*)&outVl[(size_t)r0 * N + col]       = l0;
                *(__nv_bfloat162*)&outVh[(size_t)(r0 + 8) * N + col] = h1;
                *(__nv_bfloat162*)&outVl[(size_t)(r0 + 8) * N + col] = l1;
            }
        }
        return;
    }

    float* stg = (float*)smc;
    #pragma unroll
    for (int mt = 0; mt < 4; mt++) {
        const int lr0 = wm * 64 + mt * 16 + g;
        #pragma unroll
        for (int nt = 0; nt < 4; nt++) {
            const int lc = wn * 32 + nt * 8 + tg * 2;
            const float b0 = bias[bn + lc], b1 = bias[bn + lc + 1];
            stg[lr0 * EPSTR + lc]           = acc[mt][nt][0] + b0;
            stg[lr0 * EPSTR + lc + 1]       = acc[mt][nt][1] + b1;
            stg[(lr0 + 8) * EPSTR + lc]     = acc[mt][nt][2] + b0;
            stg[(lr0 + 8) * EPSTR + lc + 1] = acc[mt][nt][3] + b1;
        }
    }
    __syncthreads();

    const float scale = (which == 0) ? 0.08838834764831845f : 1.0f;
    __nv_bfloat16* oh = (which == 0) ? outQh : outKh;
    __nv_bfloat16* ol = (which == 0) ? outQl : outKl;

    #pragma unroll 4
    for (int i = 0; i < 32; i++) {
        const int idx = tid + i * 256;
        const int row = idx >> 6;
        const int c = idx & 63;
        const int tok = bm + row;
        const int s = tok & (S_ - 1);

        const float expo = (float)(2 * c) / 128.0f;
        const float inv = 1.0f / powf(1.0e6f, expo);
        float sn, cs;
        sincosf((float)s * inv, &sn, &cs);

        const float x1 = stg[row * EPSTR + c];
        const float x2 = stg[row * EPSTR + c + 64];
        const float y1 = (x1 * cs - x2 * sn) * scale;
        const float y2 = (x2 * cs + x1 * sn) * scale;

        const __nv_bfloat16 h1 = __float2bfloat16(y1);
        const __nv_bfloat16 l1 = __float2bfloat16(y1 - __bfloat162float(h1));
        const __nv_bfloat16 h2 = __float2bfloat16(y2);
        const __nv_bfloat16 l2 = __float2bfloat16(y2 - __bfloat162float(h2));

        const size_t o1 = (size_t)tok * N + bn + c;
        oh[o1] = h1;  ol[o1] = l1;
        oh[o1 + 64] = h2;  ol[o1 + 64] = l2;
    }
}

// ============================================================================
// Out-projection GEMM (R16, unchanged)
// ============================================================================
__global__ __launch_bounds__(256, 2) void gemm_bf16x3(
    const __nv_bfloat16* __restrict__ Ah, const __nv_bfloat16* __restrict__ Al,
    const __nv_bfloat16* __restrict__ Bh, const __nv_bfloat16* __restrict__ Bl,
    float* __restrict__ C, int M, int N, int K)
{
    extern __shared__ char smc[];
    const uint32_t sb = smem_u32(smc);
    const int tid = threadIdx.x;
    const int wid = tid >> 5, lane = tid & 31;
    const int bm = blockIdx.y * 128, bn = blockIdx.x * 128;
    const int wm = wid & 1, wn = wid >> 1;
    const int g = lane >> 2, tg = lane & 3;
    const int lrow = ((lane >> 3) & 1) * 8 + (lane & 7);
    const int lcol = (lane >> 4) * 16;

    float acc[4][4][4];
    #pragma unroll
    for (int i = 0; i < 4; i++)
        #pragma unroll
        for (int j = 0; j < 4; j++)
            #pragma unroll
            for (int r = 0; r < 4; r++) acc[i][j][r] = 0.0f;

    const int T = K / 32;

    auto issue = [&](int s, int k0) {
        const uint32_t sbase = sb + s * STG;
        #pragma unroll
        for (int i = 0; i < 2; i++) {
            const int idx = tid + i * 256;
            const int row = idx >> 2, c8 = idx & 3;
            const size_t goA = (size_t)(bm + row) * K + k0 + c8 * 8;
            const size_t goB = (size_t)(bn + row) * K + k0 + c8 * 8;
            const uint32_t so = (uint32_t)(row * RSTR + c8 * 16);
            cp16(sbase + so,            Ah + goA);
            cp16(sbase + MATB + so,     Al + goA);
            cp16(sbase + 2 * MATB + so, Bh + goB);
            cp16(sbase + 3 * MATB + so, Bl + goB);
        }
        asm volatile("cp.async.commit_group;" ::: "memory");
    };

    issue(0, 0);

    for (int t = 0; t < T; t++) {
        asm volatile("cp.async.wait_group 0;" ::: "memory");
        __syncthreads();
        if (t + 1 < T) issue((t + 1) & 1, (t + 1) * 32);

        const uint32_t stb = sb + (t & 1) * STG;
        const uint32_t aLdm = stb + (uint32_t)((wm * 64 + lrow) * RSTR + lcol);
        const uint32_t bB = stb + 2 * MATB + (uint32_t)((wn * 32 + g) * RSTR + tg * 4);

        #pragma unroll
        for (int ks = 0; ks < 2; ks++) {
            const uint32_t ko = ks * 32;
            uint32_t bh[4][2], bl[4][2];
            #pragma unroll
            for (int nt = 0; nt < 4; nt++) {
                const uint32_t a = bB + nt * 8 * RSTR + ko;
                bh[nt][0] = lds32(a);
                bh[nt][1] = lds32(a + 16);
                bl[nt][0] = lds32(a + MATB);
                bl[nt][1] = lds32(a + MATB + 16);
            }
            #pragma unroll
            for (int mt = 0; mt < 4; mt++) {
                uint32_t ah[4], al[4];
                ldmx4(ah, aLdm + mt * 16 * RSTR + ko);
                ldmx4(al, aLdm + MATB + mt * 16 * RSTR + ko);
                #pragma unroll
                for (int nt = 0; nt < 4; nt++)
                    mma_bf16(acc[mt][nt], ah[0], ah[1], ah[2], ah[3],
                             bh[nt][0], bh[nt][1]);
                #pragma unroll
                for (int nt = 0; nt < 4; nt++)
                    mma_bf16(acc[mt][nt], ah[0], ah[1], ah[2], ah[3],
                             bl[nt][0], bl[nt][1]);
                #pragma unroll
                for (int nt = 0; nt < 4; nt++)
                    mma_bf16(acc[mt][nt], al[0], al[1], al[2], al[3],
                             bh[nt][0], bh[nt][1]);
            }
        }
    }

    #pragma unroll
    for (int mt = 0; mt < 4; mt++) {
        const int r0 = bm + wm * 64 + mt * 16 + g;
        #pragma unroll
        for (int nt = 0; nt < 4; nt++) {
            const int col = bn + wn * 32 + nt * 8 + tg * 2;
            *(float2*)&C[(size_t)r0 * N + col] =
                make_float2(acc[mt][nt][0], acc[mt][nt][1]);
            *(float2*)&C[(size_t)(r0 + 8) * N + col] =
                make_float2(acc[mt][nt][2], acc[mt][nt][3]);
        }
    }
}

// ============================================================================
// Tensor-core flash attention v3 (R15): 128 q-rows, 8 warps, KV double-buffer.
// qt remapped longest-first for tail balance (math unchanged).
// ============================================================================
#define FSTRB 272
#define FQTILE (128 * FSTRB)
#define FKTILE (64 * FSTRB)
#define FKSTG  (4 * FKTILE)
#define FSMEM (2 * FQTILE + 2 * FKSTG)

__global__ __launch_bounds__(256, 1) void flash_mma()
{
    extern __shared__ char smf[];
    const uint32_t sb = smem_u32(smf);
    const uint32_t QH = 0, QL = FQTILE;
    const uint32_t KV0 = 2 * FQTILE;

    const int qt = (S_ / 128 - 1) - blockIdx.x;   // longest-work CTAs first
    const int h = blockIdx.y, b = blockIdx.z;
    const int kvh = h >> 2;
    const int tid = threadIdx.x;
    const int w = tid >> 5, lane = tid & 31;
    const int g = lane >> 2, tg = lane & 3;

    const size_t kvoff = ((size_t)b * S_ * NKV_ + kvh) * HD_;
    const __nv_bfloat16* khp = g_kh + kvoff;
    const __nv_bfloat16* klp = g_kl + kvoff;
    const __nv_bfloat16* vhp = g_vh + kvoff;
    const __nv_bfloat16* vlp = g_vl + kvoff;

    auto issue_kv = [&](int jt) {
        const uint32_t kb = KV0 + (jt & 1) * FKSTG;
        const size_t tb = (size_t)(jt * 64) * KVD;
        #pragma unroll
        for (int i = 0; i < 4; i++) {
            const int c = tid + i * 256;
            const int row = c >> 4, o16 = c & 15;
            const uint32_t so = (uint32_t)(row * FSTRB + o16 * 16);
            const size_t go = tb + (size_t)row * KVD + o16 * 8;
            cp16(sb + kb + so,              khp + go);
            cp16(sb + kb + FKTILE + so,     klp + go);
            cp16(sb + kb + 2 * FKTILE + so, vhp + go);
            cp16(sb + kb + 3 * FKTILE + so, vlp + go);
        }
        asm volatile("cp.async.commit_group;" ::: "memory");
    };

    {
        const size_t qoff = (((size_t)(b * S_ + qt * 128)) * NH_ + h) * HD_;
        const __nv_bfloat16* qhp = g_qh + qoff;
        const __nv_bfloat16* qlp = g_ql + qoff;
        #pragma unroll
        for (int i = 0; i < 8; i++) {
            const int c = tid + i * 256;
            const int row = c >> 4, o16 = c & 15;
            const uint32_t so = (uint32_t)(row * FSTRB + o16 * 16);
            const size_t go = (size_t)row * (NH_ * HD_) + o16 * 8;
            cp16(sb + QH + so, qhp + go);
            cp16(sb + QL + so, qlp + go);
        }
        asm volatile("cp.async.commit_group;" ::: "memory");
    }
    issue_kv(0);

    float o[16][4];
    #pragma unroll
    for (int n = 0; n < 16; n++)
        #pragma unroll
        for (int c = 0; c < 4; c++) o[n][c] = 0.0f;
    float m0 = -1e30f, m1 = -1e30f, l0 = 0.0f, l1 = 0.0f;

    const int r0l = 16 * w + g;
    const int row_g0 = qt * 128 + r0l;
    const int jtmax = 2 * qt + 1;

    for (int jt = 0; jt <= jtmax; jt++) {
        asm volatile("cp.async.wait_group 0;" ::: "memory");
        __syncthreads();
        if (jt + 1 <= jtmax) issue_kv(jt + 1);

        const uint32_t KH = KV0 + (jt & 1) * FKSTG;
        const uint32_t VH = KH + 2 * FKTILE;

        float sacc[8][4];
        #pragma unroll
        for (int n = 0; n < 8; n++)
            #pragma unroll
            for (int c = 0; c < 4; c++) sacc[n][c] = 0.0f;

        const uint32_t qrow = sb + QH + (uint32_t)((16 * w + g) * FSTRB + tg * 4);
        #pragma unroll
        for (int k0 = 0; k0 < 8; k0++) {
            const uint32_t qa = qrow + k0 * 32;
            const uint32_t ah0 = lds32(qa);
            const uint32_t ah1 = lds32(qa + 8 * FSTRB);
            const uint32_t ah2 = lds32(qa + 16);
            const uint32_t ah3 = lds32(qa + 8 * FSTRB + 16);
            const uint32_t al0 = lds32(qa + FQTILE);
            const uint32_t al1 = lds32(qa + FQTILE + 8 * FSTRB);
            const uint32_t al2 = lds32(qa + FQTILE + 16);
            const uint32_t al3 = lds32(qa + FQTILE + 8 * FSTRB + 16);
            #pragma unroll
            for (int n = 0; n < 8; n++) {
                const uint32_t kb = sb + KH +
                    (uint32_t)((n * 8 + g) * FSTRB + k0 * 32 + tg * 4);
                const uint32_t bh0 = lds32(kb);
                const uint32_t bh1 = lds32(kb + 16);
                const uint32_t bl0 = lds32(kb + FKTILE);
                const uint32_t bl1 = lds32(kb + FKTILE + 16);
                mma_bf16(sacc[n], ah0, ah1, ah2, ah3, bh0, bh1);
                mma_bf16(sacc[n], ah0, ah1, ah2, ah3, bl0, bl1);
                mma_bf16(sacc[n], al0, al1, al2, al3, bh0, bh1);
            }
        }

        if (jt >= 2 * qt) {
            #pragma unroll
            for (int n = 0; n < 8; n++) {
                const int col_g = jt * 64 + n * 8 + 2 * tg;
                if (col_g     > row_g0)     sacc[n][0] = -1e30f;
                if (col_g + 1 > row_g0)     sacc[n][1] = -1e30f;
                if (col_g     > row_g0 + 8) sacc[n][2] = -1e30f;
                if (col_g + 1 > row_g0 + 8) sacc[n][3] = -1e30f;
            }
        }

        float mx0 = -1e30f, mx1 = -1e30f;
        #pragma unroll
        for (int n = 0; n < 8; n++) {
            mx0 = fmaxf(mx0, fmaxf(sacc[n][0], sacc[n][1]));
            mx1 = fmaxf(mx1, fmaxf(sacc[n][2], sacc[n][3]));
        }
        mx0 = fmaxf(mx0, __shfl_xor_sync(0xffffffffu, mx0, 1));
        mx0 = fmaxf(mx0, __shfl_xor_sync(0xffffffffu, mx0, 2));
        mx1 = fmaxf(mx1, __shfl_xor_sync(0xffffffffu, mx1, 1));
        mx1 = fmaxf(mx1, __shfl_xor_sync(0xffffffffu, mx1, 2));
        const float nm0 = fmaxf(m0, mx0), nm1 = fmaxf(m1, mx1);
        const float a0 = __expf(m0 - nm0), a1 = __expf(m1 - nm1);
        m0 = nm0; m1 = nm1;

        float s0 = 0.0f, s1 = 0.0f;
        #pragma unroll
        for (int n = 0; n < 8; n++) {
            sacc[n][0] = __expf(sacc[n][0] - nm0);
            sacc[n][1] = __expf(sacc[n][1] - nm0);
            sacc[n][2] = __expf(sacc[n][2] - nm1);
            sacc[n][3] = __expf(sacc[n][3] - nm1);
            s0 += sacc[n][0] + sacc[n][1];
            s1 += sacc[n][2] + sacc[n][3];
        }
        s0 += __shfl_xor_sync(0xffffffffu, s0, 1);
        s0 += __shfl_xor_sync(0xffffffffu, s0, 2);
        s1 += __shfl_xor_sync(0xffffffffu, s1, 1);
        s1 += __shfl_xor_sync(0xffffffffu, s1, 2);
        l0 = l0 * a0 + s0;
        l1 = l1 * a1 + s1;

        #pragma unroll
        for (int n = 0; n < 16; n++) {
            o[n][0] *= a0; o[n][1] *= a0;
            o[n][2] *= a1; o[n][3] *= a1;
        }

        const int mset = lane >> 3, r = lane & 7;
        #pragma unroll
        for (int kt = 0; kt < 4; kt++) {
            __nv_bfloat162 t0 = __floats2bfloat162_rn(sacc[2*kt][0],   sacc[2*kt][1]);
            __nv_bfloat162 t1 = __floats2bfloat162_rn(sacc[2*kt][2],   sacc[2*kt][3]);
            __nv_bfloat162 t2 = __floats2bfloat162_rn(sacc[2*kt+1][0], sacc[2*kt+1][1]);
            __nv_bfloat162 t3 = __floats2bfloat162_rn(sacc[2*kt+1][2], sacc[2*kt+1][3]);
            float2 f0 = __bfloat1622float2(t0), f1 = __bfloat1622float2(t1);
            float2 f2 = __bfloat1622float2(t2), f3 = __bfloat1622float2(t3);
            __nv_bfloat162 u0 = __floats2bfloat162_rn(sacc[2*kt][0]-f0.x,   sacc[2*kt][1]-f0.y);
            __nv_bfloat162 u1 = __floats2bfloat162_rn(sacc[2*kt][2]-f1.x,   sacc[2*kt][3]-f1.y);
            __nv_bfloat162 u2 = __floats2bfloat162_rn(sacc[2*kt+1][0]-f2.x, sacc[2*kt+1][1]-f2.y);
            __nv_bfloat162 u3 = __floats2bfloat162_rn(sacc[2*kt+1][2]-f3.x, sacc[2*kt+1][3]-f3.y);
            const uint32_t ph0 = *(uint32_t*)&t0, ph1 = *(uint32_t*)&t1;
            const uint32_t ph2 = *(uint32_t*)&t2, ph3 = *(uint32_t*)&t3;
            const uint32_t pl0 = *(uint32_t*)&u0, pl1 = *(uint32_t*)&u1;
            const uint32_t pl2 = *(uint32_t*)&u2, pl3 = *(uint32_t*)&u3;

            const int kk = kt * 16 + (mset & 1) * 8 + r;
            #pragma unroll
            for (int np = 0; np < 8; np++) {
                const int nn = np * 16 + (mset >> 1) * 8;
                const uint32_t va = sb + VH + (uint32_t)(kk * FSTRB + nn * 2);
                uint32_t v0, v1, v2, v3, w0, w1, w2, w3;
                ldmx4t(v0, v1, v2, v3, va);
                ldmx4t(w0, w1, w2, w3, va + FKTILE);
                mma_bf16(o[2*np],   ph0, ph1, ph2, ph3, v0, v1);
                mma_bf16(o[2*np],   ph0, ph1, ph2, ph3, w0, w1);
                mma_bf16(o[2*np],   pl0, pl1, pl2, pl3, v0, v1);
                mma_bf16(o[2*np+1], ph0, ph1, ph2, ph3, v2, v3);
                mma_bf16(o[2*np+1], ph0, ph1, ph2, ph3, w2, w3);
                mma_bf16(o[2*np+1], pl0, pl1, pl2, pl3, v2, v3);
            }
        }
    }

    const float il0 = 1.0f / l0, il1 = 1.0f / l1;
    const size_t base0 = (((size_t)(b * S_ + qt * 128 + 16 * w + g)) * NH_ + h) * HD_;
    const size_t base1 = base0 + (size_t)8 * NH_ * HD_;
    #pragma unroll
    for (int n = 0; n < 16; n++) {
        const int cc = n * 8 + tg * 2;
        const float a0 = o[n][0] * il0, a1 = o[n][1] * il0;
        const float b0v = o[n][2] * il1, b1v = o[n][3] * il1;
        __nv_bfloat162 h0 = __floats2bfloat162_rn(a0, a1);
        float2 f0 = __bfloat1622float2(h0);
        __nv_bfloat162 lo0 = __floats2bfloat162_rn(a0 - f0.x, a1 - f0.y);
        __nv_bfloat162 h1 = __floats2bfloat162_rn(b0v, b1v);
        float2 f1 = __bfloat1622float2(h1);
        __nv_bfloat162 lo1 = __floats2bfloat162_rn(b0v - f1.x, b1v - f1.y);
        *(__nv_bfloat162*)&g_ch[base0 + cc] = h0;
        *(__nv_bfloat162*)&g_cl[base0 + cc] = lo0;
        *(__nv_bfloat162*)&g_ch[base1 + cc] = h1;
        *(__nv_bfloat162*)&g_cl[base1 + cc] = lo1;
    }
}

// ---------------------------------------------------------------------------
extern "C" void kernel_launch(void* const* d_in, const int* in_sizes, int n_in,
                              void* d_out, int out_size)
{
    (void)in_sizes; (void)n_in; (void)out_size;
    const float* x    = (const float*)d_in[0];
    const float* wq_w = (const float*)d_in[1];
    const float* wq_b = (const float*)d_in[2];
    const float* wk_w = (const float*)d_in[3];
    const float* wk_b = (const float*)d_in[4];
    const float* wv_w = (const float*)d_in[5];
    const float* wv_b = (const float*)d_in[6];
    const float* wo_w = (const float*)d_in[7];
    float* out = (float*)d_out;

    __nv_bfloat16 *xh, *xl, *wqh, *wql, *wkh, *wkl, *wvh, *wvl, *woh, *wol, *ch, *cl;
    __nv_bfloat16 *qh, *ql, *kh, *kl, *vh, *vl;
    cudaGetSymbolAddress((void**)&xh,  g_xh);  cudaGetSymbolAddress((void**)&xl,  g_xl);
    cudaGetSymbolAddress((void**)&wqh, g_wqh); cudaGetSymbolAddress((void**)&wql, g_wql);
    cudaGetSymbolAddress((void**)&wkh, g_wkh); cudaGetSymbolAddress((void**)&wkl, g_wkl);
    cudaGetSymbolAddress((void**)&wvh, g_wvh); cudaGetSymbolAddress((void**)&wvl, g_wvl);
    cudaGetSymbolAddress((void**)&woh, g_woh); cudaGetSymbolAddress((void**)&wol, g_wol);
    cudaGetSymbolAddress((void**)&ch,  g_ch);  cudaGetSymbolAddress((void**)&cl,  g_cl);
    cudaGetSymbolAddress((void**)&qh,  g_qh);  cudaGetSymbolAddress((void**)&ql,  g_ql);
    cudaGetSymbolAddress((void**)&kh,  g_kh);  cudaGetSymbolAddress((void**)&kl,  g_kl);
    cudaGetSymbolAddress((void**)&vh,  g_vh);  cudaGetSymbolAddress((void**)&vl,  g_vl);

    cudaFuncSetAttribute(qkv_gemm, cudaFuncAttributeMaxDynamicSharedMemorySize,
                         SMEM_GEMM);
    cudaFuncSetAttribute(gemm_bf16x3, cudaFuncAttributeMaxDynamicSharedMemorySize,
                         SMEM_GEMM);
    cudaFuncSetAttribute(flash_mma, cudaFuncAttributeMaxDynamicSharedMemorySize,
                         FSMEM);

    // fused hi/lo splits of x and all weights (one launch)
    split_all<<<SPLIT_GRID, 256>>>(x, wq_w, wk_w, wv_w, wo_w,
                                   xh, xl, wqh, wql, wkh, wkl,
                                   wvh, wvl, woh, wol);

    // fused QKV projections + RoPE + bf16 split (Q scaled by 1/sqrt(HD))
    qkv_gemm<<<1536, 256, SMEM_GEMM>>>(
        xh, xl, wqh, wql, wkh, wkl, wvh, wvl,
        wq_b, wk_b, wv_b, qh, ql, kh, kl, vh, vl);

    // tensor-core causal GQA flash attention (128 q-rows, KV double-buffered)
    flash_mma<<<dim3(S_ / 128, NH_, B_), 256, FSMEM>>>();

    // output projection (no bias)
    gemm_bf16x3<<<dim3(D_ / 128, MTOK / 128), 256, SMEM_GEMM>>>(
        ch, cl, woh, wol, out, MTOK, D_, D_);
}